// round 7
// baseline (speedup 1.0000x reference)
#include <cuda_runtime.h>
#include <cuda_fp16.h>
#include <cstdint>
#include <cstddef>

#define I_DIM 512
#define O_DIM 512
#define KDIM  4096          // I_DIM * 8 degrees
#define TILE_M 128
#define TILE_N 128
#define KC     64           // K elems per chunk (8 i's x 8 degrees)
#define NCHUNK (KDIM / KC)  // 64
#define THREADS 256
#define PITCH  144          // bytes per row: 64 halves (128B) + 16B pad = 36 words

#define COEF_SCALE   1024.0f
#define OUT_SCALE    (1.0f / 1024.0f)

// Transposed, scaled fp16 coefficients: Wh[o][k], k = i*8 + d
__device__ __align__(16) __half g_Wh[(size_t)O_DIM * KDIM];

// ---------------- helpers ----------------
__device__ __forceinline__ uint32_t smem_u32(const void* p) {
    uint32_t a;
    asm("{ .reg .u64 t; cvta.to.shared.u64 t, %1; cvt.u32.u64 %0, t; }"
        : "=r"(a) : "l"(p));
    return a;
}

__device__ __forceinline__ uint32_t lds32(uint32_t a) {
    uint32_t v;
    asm volatile("ld.shared.b32 %0, [%1];" : "=r"(v) : "r"(a));
    return v;
}

__device__ __forceinline__ void sts128(uint32_t a, uint32_t v0, uint32_t v1,
                                       uint32_t v2, uint32_t v3) {
    asm volatile("st.shared.v4.b32 [%0], {%1,%2,%3,%4};"
                 :: "r"(a), "r"(v0), "r"(v1), "r"(v2), "r"(v3) : "memory");
}

// m16n8k16 fp16 MMA, f32 accumulate
__device__ __forceinline__ void mma16(float* c, const uint32_t* a, const uint32_t* b) {
    asm volatile(
        "mma.sync.aligned.m16n8k16.row.col.f32.f16.f16.f32 "
        "{%0,%1,%2,%3}, {%4,%5,%6,%7}, {%8,%9}, {%0,%1,%2,%3};"
        : "+f"(c[0]), "+f"(c[1]), "+f"(c[2]), "+f"(c[3])
        : "r"(a[0]), "r"(a[1]), "r"(a[2]), "r"(a[3]), "r"(b[0]), "r"(b[1]));
}

__device__ __forceinline__ uint32_t pack_h2(float lo, float hi) {
    __half2 h = __floats2half2_rn(lo, hi);
    return *reinterpret_cast<uint32_t*>(&h);
}

// accurate-enough tanh: 1 - 2/(exp(2x)+1); MUFU-based, err ~1e-6
__device__ __forceinline__ float fast_tanh(float x) {
    float e = __expf(2.0f * x);
    return 1.0f - __fdividef(2.0f, e + 1.0f);
}

// ---------------- kernel 0: transpose + scale coeffs to fp16 ----------------
__global__ void prep_kernel(const float* __restrict__ coeffs) {
    int idx = blockIdx.x * blockDim.x + threadIdx.x;   // coalesced read
    int i = idx >> 12;
    int o = (idx >> 3) & 511;
    int d = idx & 7;
    g_Wh[((size_t)o << 12) + (i << 3) + d] =
        __float2half_rn(coeffs[idx] * COEF_SCALE);
}

// ---------------- kernel 1: fused poly + fp16 mma GEMM, 2 CTAs/SM ----------------
// A stage = 128*144 = 18432 B, B stage = 18432 B; double buffered = 73728 B
#define A_STRIDE 18432u
#define B_STRIDE 18432u
#define B_BASE   (2u * A_STRIDE)
#define SMEM_BYTES (2 * (18432 + 18432))   // 73728

__global__ void __launch_bounds__(THREADS, 2)
gegen_kernel(const float* __restrict__ x, float* __restrict__ out) {
    extern __shared__ __align__(16) char smem[];
    const uint32_t sb = smem_u32(smem);
    const int tid  = threadIdx.x;
    const int lane = tid & 31;
    const int wid  = tid >> 5;
    const int b0 = blockIdx.x * TILE_M;
    const int o0 = blockIdx.y * TILE_N;
    const int wm = (wid & 3) * 32;     // warp m offset (4 warps in M)
    const int wn = (wid >> 2) * 64;    // warp n offset (2 warps in N)

    uint32_t aBase[2], bBase[2];
#pragma unroll
    for (int s = 0; s < 2; s++) {
        aBase[s] = sb + s * A_STRIDE;
        bBase[s] = sb + B_BASE + s * B_STRIDE;
    }

    float acc[2][8][4];
#pragma unroll
    for (int mf = 0; mf < 2; mf++)
#pragma unroll
        for (int nf = 0; nf < 8; nf++)
#pragma unroll
            for (int j = 0; j < 4; j++) acc[mf][nf][j] = 0.0f;

    // producer bases: 2 threads per row; half = tid&1 covers 4 i's (= 32 k)
    const int prow = tid >> 1;
    const int half = tid & 1;
    const float* xrow = x + (size_t)(b0 + prow) * I_DIM + half * 4;
    const __half* wrow = g_Wh + ((size_t)(o0 + prow) << 12) + half * 32;
    const uint32_t a_sts = prow * PITCH + half * 64;    // + ii*16
    const uint32_t b_sts = prow * PITCH + half * 64;    // + j*16

    // ---- produce chunk c; xv = x[c*8 + half*4 .. +3] ----
    auto produce = [&](int c, uint32_t aBuf, uint32_t bBuf, const float4& xv) {
        const __half* src = wrow + c * KC;
#pragma unroll
        for (int j = 0; j < 4; j++) {
            asm volatile("cp.async.cg.shared.global [%0], [%1], 16;"
                         :: "r"(bBuf + b_sts + j * 16), "l"(src + j * 8)
                         : "memory");
        }
        const float xs[4] = {xv.x, xv.y, xv.z, xv.w};
#pragma unroll
        for (int ii = 0; ii < 4; ii++) {
            float t  = fast_tanh(xs[ii]);
            float t2 = t + t;
            float c0 = 1.0f, c1 = t2;
            float c2 = fmaf(t2, c1, -c0);
            float c3 = fmaf(t2, c2, -c1);
            float c4 = fmaf(t2, c3, -c2);
            float c5 = fmaf(t2, c4, -c3);
            float c6 = fmaf(t2, c5, -c4);
            float c7 = fmaf(t2, c6, -c5);
            sts128(aBuf + a_sts + ii * 16,
                   pack_h2(c0, c1), pack_h2(c2, c3),
                   pack_h2(c4, c5), pack_h2(c6, c7));
        }
    };

    // ---- consume one chunk (4 k-steps, no frag double-buffer) ----
    auto consume = [&](uint32_t aBuf, uint32_t bBuf) {
#pragma unroll
        for (int ks = 0; ks < 4; ks++) {
            uint32_t a[2][4], b[8][2];
            const uint32_t koff = ks * 32 + (lane & 3) * 4;
#pragma unroll
            for (int mf = 0; mf < 2; mf++) {
                uint32_t base = aBuf + (wm + mf * 16 + (lane >> 2)) * PITCH + koff;
                a[mf][0] = lds32(base);
                a[mf][1] = lds32(base + 8 * PITCH);
                a[mf][2] = lds32(base + 16);
                a[mf][3] = lds32(base + 8 * PITCH + 16);
            }
#pragma unroll
            for (int nf = 0; nf < 8; nf++) {
                uint32_t base = bBuf + (wn + nf * 8 + (lane >> 2)) * PITCH + koff;
                b[nf][0] = lds32(base);
                b[nf][1] = lds32(base + 16);
            }
#pragma unroll
            for (int mf = 0; mf < 2; mf++)
#pragma unroll
                for (int nf = 0; nf < 8; nf++)
                    mma16(acc[mf][nf], a[mf], b[nf]);
        }
    };

    // ---- prologue ----
    float4 xv = *reinterpret_cast<const float4*>(xrow);
    produce(0, aBase[0], bBase[0], xv);
    asm volatile("cp.async.commit_group;" ::: "memory");
    xv = *reinterpret_cast<const float4*>(xrow + 8);     // chunk 1

    // ---- main loop: one barrier per chunk; produce(c+1) then consume(c) ----
#pragma unroll 1
    for (int c = 0; c < NCHUNK; c++) {
        asm volatile("cp.async.wait_group 0;" ::: "memory");
        __syncthreads();   // chunk c visible; buffer (c+1)&1 free

        if (c + 1 < NCHUNK) {
            produce(c + 1, aBase[(c + 1) & 1], bBase[(c + 1) & 1], xv);
            asm volatile("cp.async.commit_group;" ::: "memory");
            if (c + 2 < NCHUNK)
                xv = *reinterpret_cast<const float4*>(xrow + (c + 2) * 8);
        }
        consume(aBase[c & 1], bBase[c & 1]);
    }

    // ---- epilogue: scale back and store ----
#pragma unroll
    for (int mf = 0; mf < 2; mf++) {
        const int rbase = b0 + wm + mf * 16 + (lane >> 2);
#pragma unroll
        for (int h = 0; h < 2; h++) {
            float* op = out + (size_t)(rbase + h * 8) * O_DIM
                            + o0 + wn + (lane & 3) * 2;
#pragma unroll
            for (int nf = 0; nf < 8; nf++) {
                float2 v;
                v.x = acc[mf][nf][h * 2]     * OUT_SCALE;
                v.y = acc[mf][nf][h * 2 + 1] * OUT_SCALE;
                *reinterpret_cast<float2*>(op + nf * 8) = v;
            }
        }
    }
}

// ---------------- launch ----------------
extern "C" void kernel_launch(void* const* d_in, const int* in_sizes, int n_in,
                              void* d_out, int out_size) {
    const float* x      = (const float*)d_in[0];
    const float* coeffs = (const float*)d_in[1];
    float* out          = (float*)d_out;

    const int B = in_sizes[0] / I_DIM;   // 16384

    prep_kernel<<<(I_DIM * O_DIM * 8) / 256, 256>>>(coeffs);

    cudaFuncSetAttribute(gegen_kernel,
                         cudaFuncAttributeMaxDynamicSharedMemorySize, SMEM_BYTES);

    dim3 grid(B / TILE_M, O_DIM / TILE_N);
    gegen_kernel<<<grid, THREADS, SMEM_BYTES>>>(x, out);
}

// round 8
// speedup vs baseline: 1.1868x; 1.1868x over previous
#include <cuda_runtime.h>
#include <cuda_fp16.h>
#include <cstdint>
#include <cstddef>

#define I_DIM 512
#define O_DIM 512
#define KDIM  4096          // I_DIM * 8 degrees
#define TILE_M 256
#define TILE_N 128
#define KC     64           // K elems per chunk (8 i's x 8 degrees)
#define NCHUNK (KDIM / KC)  // 64
#define THREADS 256
#define PITCH  144          // 64 halves (128B) + 16B pad; 36 words -> +4 banks/row

#define COEF_SCALE   1024.0f
#define OUT_SCALE    (1.0f / 1024.0f)

// Transposed, scaled fp16 coefficients: Wh[o][k], k = i*8 + d
__device__ __align__(16) __half g_Wh[(size_t)O_DIM * KDIM];

// ---------------- helpers ----------------
__device__ __forceinline__ uint32_t smem_u32(const void* p) {
    uint32_t a;
    asm("{ .reg .u64 t; cvta.to.shared.u64 t, %1; cvt.u32.u64 %0, t; }"
        : "=r"(a) : "l"(p));
    return a;
}

__device__ __forceinline__ void sts128(uint32_t a, uint32_t v0, uint32_t v1,
                                       uint32_t v2, uint32_t v3) {
    asm volatile("st.shared.v4.b32 [%0], {%1,%2,%3,%4};"
                 :: "r"(a), "r"(v0), "r"(v1), "r"(v2), "r"(v3) : "memory");
}

__device__ __forceinline__ void ldsm4(uint32_t* r, uint32_t addr) {
    asm volatile("ldmatrix.sync.aligned.m8n8.x4.shared.b16 {%0,%1,%2,%3}, [%4];"
                 : "=r"(r[0]), "=r"(r[1]), "=r"(r[2]), "=r"(r[3]) : "r"(addr));
}

// m16n8k16 fp16 MMA, f32 accumulate
__device__ __forceinline__ void mma16(float* c, const uint32_t* a, const uint32_t* b) {
    asm volatile(
        "mma.sync.aligned.m16n8k16.row.col.f32.f16.f16.f32 "
        "{%0,%1,%2,%3}, {%4,%5,%6,%7}, {%8,%9}, {%0,%1,%2,%3};"
        : "+f"(c[0]), "+f"(c[1]), "+f"(c[2]), "+f"(c[3])
        : "r"(a[0]), "r"(a[1]), "r"(a[2]), "r"(a[3]), "r"(b[0]), "r"(b[1]));
}

__device__ __forceinline__ uint32_t pack_h2(float lo, float hi) {
    __half2 h = __floats2half2_rn(lo, hi);
    return *reinterpret_cast<uint32_t*>(&h);
}

// accurate-enough tanh: 1 - 2/(exp(2x)+1); MUFU-based, err ~1e-6
__device__ __forceinline__ float fast_tanh(float x) {
    float e = __expf(2.0f * x);
    return 1.0f - __fdividef(2.0f, e + 1.0f);
}

// ---------------- kernel 0: transpose + scale coeffs to fp16 ----------------
__global__ void prep_kernel(const float* __restrict__ coeffs) {
    int idx = blockIdx.x * blockDim.x + threadIdx.x;   // coalesced read
    int i = idx >> 12;
    int o = (idx >> 3) & 511;
    int d = idx & 7;
    g_Wh[((size_t)o << 12) + (i << 3) + d] =
        __float2half_rn(coeffs[idx] * COEF_SCALE);
}

// ---------------- kernel 1: fused poly + fp16 mma GEMM ----------------
// A stage = 256*144 = 36864 B, B stage = 128*144 = 18432 B; double buffered
#define A_STRIDE 36864u
#define B_STRIDE 18432u
#define B_BASE   (2u * A_STRIDE)
#define SMEM_BYTES (2 * (36864 + 18432))   // 110592

__global__ void __launch_bounds__(THREADS, 1)
gegen_kernel(const float* __restrict__ x, float* __restrict__ out) {
    extern __shared__ __align__(16) char smem[];
    const uint32_t sb = smem_u32(smem);
    const int tid  = threadIdx.x;
    const int lane = tid & 31;
    const int wid  = tid >> 5;
    const int b0 = blockIdx.x * TILE_M;
    const int o0 = blockIdx.y * TILE_N;
    const int wm = (wid & 3) * 64;     // warp m offset (4 warps in M)
    const int wn = (wid >> 2) * 64;    // warp n offset (2 warps in N)

    uint32_t aBase[2], bBase[2];
#pragma unroll
    for (int s = 0; s < 2; s++) {
        aBase[s] = sb + s * A_STRIDE;
        bBase[s] = sb + B_BASE + s * B_STRIDE;
    }

    float acc[4][8][4];
#pragma unroll
    for (int mf = 0; mf < 4; mf++)
#pragma unroll
        for (int nf = 0; nf < 8; nf++)
#pragma unroll
            for (int j = 0; j < 4; j++) acc[mf][nf][j] = 0.0f;

    // ---- ldmatrix per-lane offsets (relative to stage base) ----
    // A (m16n16 tiles): matrices (m0-7,k0-7),(m8-15,k0-7),(m0-7,k8-15),(m8-15,k8-15)
    const int a_r = lane & 15;
    const int a_c = (lane >> 4) * 16;
    uint32_t aoff[4];
#pragma unroll
    for (int mf = 0; mf < 4; mf++)
        aoff[mf] = (uint32_t)(wm + mf * 16 + a_r) * PITCH + a_c;
    // B (n16 x k16 tiles): matrices (n0-7,k0-7),(n0-7,k8-15),(n8-15,k0-7),(n8-15,k8-15)
    const int b_r = (lane & 7) + ((lane >> 4) & 1) * 8;
    const int b_c = ((lane >> 3) & 1) * 16;
    uint32_t boff[4];
#pragma unroll
    for (int p = 0; p < 4; p++)
        boff[p] = (uint32_t)(wn + p * 16 + b_r) * PITCH + b_c;

    // ---- producer bases: one thread per m-row; 8 i's per chunk ----
    const float* xrow = x + (size_t)(b0 + tid) * I_DIM;
    const __half* wrow = g_Wh + ((size_t)(o0 + (tid >> 1)) << 12) + (tid & 1) * 32;
    const uint32_t a_sts = tid * PITCH;
    const uint32_t b_sts = (tid >> 1) * PITCH + (tid & 1) * 64;

    auto cp_b = [&](int c, uint32_t bBuf) {
        const __half* src = wrow + c * KC;
#pragma unroll
        for (int j = 0; j < 4; j++) {
            asm volatile("cp.async.cg.shared.global [%0], [%1], 16;"
                         :: "r"(bBuf + b_sts + j * 16), "l"(src + j * 8)
                         : "memory");
        }
        asm volatile("cp.async.commit_group;" ::: "memory");
    };

    auto produce_a = [&](uint32_t aBuf, const float4& x0, const float4& x1) {
        const float xv[8] = {x0.x, x0.y, x0.z, x0.w, x1.x, x1.y, x1.z, x1.w};
#pragma unroll
        for (int ii = 0; ii < 8; ii++) {
            float t  = fast_tanh(xv[ii]);
            float t2 = t + t;
            float c0 = 1.0f, c1 = t2;
            float c2 = fmaf(t2, c1, -c0);
            float c3 = fmaf(t2, c2, -c1);
            float c4 = fmaf(t2, c3, -c2);
            float c5 = fmaf(t2, c4, -c3);
            float c6 = fmaf(t2, c5, -c4);
            float c7 = fmaf(t2, c6, -c5);
            sts128(aBuf + a_sts + ii * 16,
                   pack_h2(c0, c1), pack_h2(c2, c3),
                   pack_h2(c4, c5), pack_h2(c6, c7));
        }
    };

    // ---- consume one chunk: 4 k-steps, ldmatrix + HMMA ----
    auto consume = [&](uint32_t aBuf, uint32_t bBuf) {
#pragma unroll
        for (int ks = 0; ks < 4; ks++) {
            const uint32_t koff = ks * 32;
            uint32_t a[4][4], b[4][4];
#pragma unroll
            for (int mf = 0; mf < 4; mf++) ldsm4(a[mf], aBuf + aoff[mf] + koff);
#pragma unroll
            for (int p = 0; p < 4; p++)   ldsm4(b[p], bBuf + boff[p] + koff);
#pragma unroll
            for (int mf = 0; mf < 4; mf++)
#pragma unroll
                for (int nf = 0; nf < 8; nf++)
                    mma16(acc[mf][nf], a[mf], &b[nf >> 1][(nf & 1) * 2]);
        }
    };

    // ---- prologue: fill chunk 0 ----
    float4 xa = *reinterpret_cast<const float4*>(xrow);
    float4 xb = *reinterpret_cast<const float4*>(xrow + 4);
    cp_b(0, bBase[0]);
    produce_a(aBase[0], xa, xb);
    xa = *reinterpret_cast<const float4*>(xrow + 8);      // chunk 1
    xb = *reinterpret_cast<const float4*>(xrow + 12);

    // ---- main loop: sync -> cp.async(c+1) -> consume(c) -> produce_a(c+1) ----
#pragma unroll 1
    for (int c = 0; c < NCHUNK; c++) {
        asm volatile("cp.async.wait_group 0;" ::: "memory");
        __syncthreads();   // chunk c (A STS + B cp.async) visible; buf (c+1)&1 free

        const int cur = c & 1, nxt = cur ^ 1;
        if (c + 1 < NCHUNK) cp_b(c + 1, bBase[nxt]);

        consume(aBase[cur], bBase[cur]);

        if (c + 1 < NCHUNK) {
            produce_a(aBase[nxt], xa, xb);
            if (c + 2 < NCHUNK) {
                xa = *reinterpret_cast<const float4*>(xrow + (c + 2) * 8);
                xb = *reinterpret_cast<const float4*>(xrow + (c + 2) * 8 + 4);
            }
        }
    }

    // ---- epilogue: scale back and store ----
#pragma unroll
    for (int mf = 0; mf < 4; mf++) {
        const int rbase = b0 + wm + mf * 16 + (lane >> 2);
#pragma unroll
        for (int h = 0; h < 2; h++) {
            float* op = out + (size_t)(rbase + h * 8) * O_DIM
                            + o0 + wn + (lane & 3) * 2;
#pragma unroll
            for (int nf = 0; nf < 8; nf++) {
                float2 v;
                v.x = acc[mf][nf][h * 2]     * OUT_SCALE;
                v.y = acc[mf][nf][h * 2 + 1] * OUT_SCALE;
                *reinterpret_cast<float2*>(op + nf * 8) = v;
            }
        }
    }
}

// ---------------- launch ----------------
extern "C" void kernel_launch(void* const* d_in, const int* in_sizes, int n_in,
                              void* d_out, int out_size) {
    const float* x      = (const float*)d_in[0];
    const float* coeffs = (const float*)d_in[1];
    float* out          = (float*)d_out;

    const int B = in_sizes[0] / I_DIM;   // 16384

    prep_kernel<<<(I_DIM * O_DIM * 8) / 256, 256>>>(coeffs);

    cudaFuncSetAttribute(gegen_kernel,
                         cudaFuncAttributeMaxDynamicSharedMemorySize, SMEM_BYTES);

    dim3 grid(B / TILE_M, O_DIM / TILE_N);
    gegen_kernel<<<grid, THREADS, SMEM_BYTES>>>(x, out);
}